// round 3
// baseline (speedup 1.0000x reference)
#include <cuda_runtime.h>
#include <cuda_bf16.h>
#include <math.h>

#define NB 8
#define BATCH 256
#define NV 14062
#define NV3 (NV*3)
#define KD 120          // 63 pose-corrective (bones 1-7) + 55 bsw + 1 (T) + 1 pad
#define KC 24           // k-chunk (coef regs per lane)
#define NCH 5           // KD / KC
#define BMB 32          // batches per block (lane = batch)
#define BVV 64          // verts per block
#define BVC 192         // comps per block = BVV*3
#define STG_PITCH 193   // staging row pitch (conflict-free)

// scratch (allocation-free requirement -> device globals)
__device__ float g_coef[BATCH * KD];        // [b][k]
__device__ float g_bone[BATCH * NB * 12];   // [b][n][3x4 row-major]

struct Aff { float r[9]; float t[3]; };

__device__ __forceinline__ Aff amul(const Aff& A, const Aff& B) {
    Aff C;
#pragma unroll
    for (int i = 0; i < 3; i++) {
#pragma unroll
        for (int j = 0; j < 3; j++) {
            C.r[i*3+j] = A.r[i*3+0]*B.r[0*3+j] + A.r[i*3+1]*B.r[1*3+j] + A.r[i*3+2]*B.r[2*3+j];
        }
        C.t[i] = A.r[i*3+0]*B.t[0] + A.r[i*3+1]*B.t[1] + A.r[i*3+2]*B.t[2] + A.t[i];
    }
    return C;
}

__device__ __forceinline__ Aff ainv_rigid(const Aff& A) {
    Aff C;
#pragma unroll
    for (int i = 0; i < 3; i++)
#pragma unroll
        for (int j = 0; j < 3; j++)
            C.r[i*3+j] = A.r[j*3+i];
#pragma unroll
    for (int i = 0; i < 3; i++)
        C.t[i] = -(C.r[i*3+0]*A.t[0] + C.r[i*3+1]*A.t[1] + C.r[i*3+2]*A.t[2]);
    return C;
}

__device__ __forceinline__ void rodrigues(const float* rv, float* R) {
    float x = rv[0], y = rv[1], z = rv[2];
    float d = x*x + y*y + z*z + 1e-12f;
    float ang = sqrtf(d);
    float inv = 1.0f / ang;
    float kx = x*inv, ky = y*inv, kz = z*inv;
    float s = sinf(ang), c = cosf(ang);
    float kk = kx*kx + ky*ky + kz*kz;   // match reference's literal K@K
    float oc = 1.0f - c;
    R[0] = 1.0f + oc*(kx*kx - kk);
    R[1] = -s*kz + oc*(kx*ky);
    R[2] =  s*ky + oc*(kx*kz);
    R[3] =  s*kz + oc*(ky*kx);
    R[4] = 1.0f + oc*(ky*ky - kk);
    R[5] = -s*kx + oc*(ky*kz);
    R[6] = -s*ky + oc*(kz*kx);
    R[7] =  s*kx + oc*(kz*ky);
    R[8] = 1.0f + oc*(kz*kz - kk);
}

// One thread per batch: Rodrigues + FK chain + inverse binds + coef vector.
// Coef layout (bone 0's theta_zero is identically 0 -> dropped):
//   [0..62]   bones 1..7 theta_zero (row-major 3x3 each)
//   [63..117] bsw (55)
//   [118]     1.0 (T row)
//   [119]     0.0 (pad)
__global__ void prep_kernel(const float* __restrict__ theta,
                            const float* __restrict__ bsw,
                            const float* __restrict__ L2P) {
    int b = threadIdx.x;
    if (b >= BATCH) return;

    float R[NB][9];
#pragma unroll
    for (int n = 0; n < NB; n++)
        rodrigues(theta + (b*NB + n)*3, R[n]);

    float* c = g_coef + b*KD;
#pragma unroll
    for (int n = 1; n < NB; n++)
#pragma unroll
        for (int i = 0; i < 3; i++)
#pragma unroll
            for (int j = 0; j < 3; j++)
                c[(n-1)*9 + i*3 + j] = R[n][i*3+j] - (i == j ? 1.0f : 0.0f);
    for (int j = 0; j < 55; j++) c[63 + j] = bsw[b*55 + j];
    c[118] = 1.0f;
    c[119] = 0.0f;

    Aff M, rest;
#pragma unroll
    for (int n = 0; n < NB; n++) {
        Aff l2p;
#pragma unroll
        for (int i = 0; i < 3; i++) {
#pragma unroll
            for (int j = 0; j < 3; j++) l2p.r[i*3+j] = L2P[n*16 + i*4 + j];
            l2p.t[i] = L2P[n*16 + i*4 + 3];
        }
        Aff loc;
#pragma unroll
        for (int i = 0; i < 9; i++) loc.r[i] = R[n][i];
        loc.t[0] = loc.t[1] = loc.t[2] = 0.0f;

        Aff An = amul(l2p, loc);
        M    = (n == 0) ? An  : amul(M, An);
        rest = (n == 0) ? l2p : amul(rest, l2p);

        Aff w2l = ainv_rigid(rest);
        Aff G = amul(M, w2l);

        float* g = g_bone + b*(NB*12) + n*12;
#pragma unroll
        for (int i = 0; i < 3; i++) {
            g[i*4+0] = G.r[i*3+0];
            g[i*4+1] = G.r[i*3+1];
            g[i*4+2] = G.r[i*3+2];
            g[i*4+3] = G.t[i];
        }
    }
}

// Main kernel. lane = batch (coef in registers), warp = 24 vcomps (8 verts).
// Basis operand read from shared via pure-broadcast LDS.128 (1 wavefront).
// Output staged in shared and copied out coalesced.
__global__ __launch_bounds__(256, 3)
void hack_main_kernel(const float* __restrict__ P,
                      const float* __restrict__ E,
                      const float* __restrict__ T,
                      const float* __restrict__ W,
                      const float* __restrict__ ts,
                      const float* __restrict__ uvgrid,
                      const float* __restrict__ L,
                      const float* __restrict__ tau,
                      const float* __restrict__ alpha,
                      float* __restrict__ out) {
    __shared__ float sm[BMB * STG_PITCH];   // 6176 floats; also holds KC*BVC=4608 basis tile

    const int tid  = threadIdx.x;
    const int lane = tid & 31;
    const int w    = tid >> 5;              // warp id 0..7
    const int v0   = blockIdx.x * BVV;
    const int b0   = blockIdx.y * BMB;
    const int b    = b0 + lane;

    float acc[24];
#pragma unroll
    for (int q = 0; q < 24; q++) acc[q] = 0.0f;

    for (int kc = 0; kc < NCH; kc++) {
        // per-lane coefficient chunk -> registers (global, L2/L1 hot)
        float cr[KC];
        {
            const float4* cp = (const float4*)(g_coef + b*KD + kc*KC);
#pragma unroll
            for (int j = 0; j < KC/4; j++) {
                float4 t = cp[j];
                cr[j*4+0] = t.x; cr[j*4+1] = t.y; cr[j*4+2] = t.z; cr[j*4+3] = t.w;
            }
        }

        __syncthreads();   // previous chunk's readers done before overwrite
        // basis tile [KC][BVC] from P / E / T
        for (int i = tid; i < KC * BVC; i += 256) {
            int kl  = i / BVC;
            int col = i - kl * BVC;
            int k   = kc * KC + kl;
            int v   = v0 + col / 3;
            int cc  = col - (col/3)*3;
            float val = 0.0f;
            if (v < NV) {
                if (k < 63)        val = P[(k+9)*NV3 + v*3 + cc];
                else if (k < 118)  val = E[(k-63)*NV3 + v*3 + cc];
                else if (k == 118) val = T[v*3 + cc];
            }
            sm[kl*BVC + col] = val;
        }
        __syncthreads();

        const float4* bp = ((const float4*)sm) + w * 6;   // this warp's 24 comps
#pragma unroll
        for (int kk = 0; kk < KC; kk++) {
            float a = cr[kk];
            float4 q0 = bp[kk*48 + 0];   // broadcast LDS.128 (all lanes same addr)
            float4 q1 = bp[kk*48 + 1];
            float4 q2 = bp[kk*48 + 2];
            float4 q3 = bp[kk*48 + 3];
            float4 q4 = bp[kk*48 + 4];
            float4 q5 = bp[kk*48 + 5];
            acc[ 0] = fmaf(a, q0.x, acc[ 0]); acc[ 1] = fmaf(a, q0.y, acc[ 1]);
            acc[ 2] = fmaf(a, q0.z, acc[ 2]); acc[ 3] = fmaf(a, q0.w, acc[ 3]);
            acc[ 4] = fmaf(a, q1.x, acc[ 4]); acc[ 5] = fmaf(a, q1.y, acc[ 5]);
            acc[ 6] = fmaf(a, q1.z, acc[ 6]); acc[ 7] = fmaf(a, q1.w, acc[ 7]);
            acc[ 8] = fmaf(a, q2.x, acc[ 8]); acc[ 9] = fmaf(a, q2.y, acc[ 9]);
            acc[10] = fmaf(a, q2.z, acc[10]); acc[11] = fmaf(a, q2.w, acc[11]);
            acc[12] = fmaf(a, q3.x, acc[12]); acc[13] = fmaf(a, q3.y, acc[13]);
            acc[14] = fmaf(a, q3.z, acc[14]); acc[15] = fmaf(a, q3.w, acc[15]);
            acc[16] = fmaf(a, q4.x, acc[16]); acc[17] = fmaf(a, q4.y, acc[17]);
            acc[18] = fmaf(a, q4.z, acc[18]); acc[19] = fmaf(a, q4.w, acc[19]);
            acc[20] = fmaf(a, q5.x, acc[20]); acc[21] = fmaf(a, q5.y, acc[21]);
            acc[22] = fmaf(a, q5.z, acc[22]); acc[23] = fmaf(a, q5.w, acc[23]);
        }
    }

    __syncthreads();   // sB dead; reuse sm as output staging [32][STG_PITCH]

    // Epilogue: larynx displacement + skinning, results into staging smem.
    {
        const float al = alpha[b];
        const float tb = tau[b];
        const int vbase = v0 + w * 8;
        const float4* Gb = (const float4*)(g_bone + b*(NB*12));

#pragma unroll
        for (int vl = 0; vl < 8; vl++) {
            const int v = vbase + vl;
            if (v < NV) {
                // bilinear sample of L (256x256), align_corners=True, border clamp
                float ux = uvgrid[v*2+0], uy = uvgrid[v*2+1];
                float x = fminf(fmaxf(ux * 255.0f, 0.0f), 255.0f);
                float y = fminf(fmaxf((uy + tb) * 255.0f, 0.0f), 255.0f);
                int x0 = (int)floorf(x), y0 = (int)floorf(y);
                int x1 = min(x0 + 1, 255), y1 = min(y0 + 1, 255);
                float wx = x - (float)x0, wy = y - (float)y0;
                float v00 = L[y0*256 + x0], v01 = L[y0*256 + x1];
                float v10 = L[y1*256 + x0], v11 = L[y1*256 + x1];
                float dist = (v00*(1.0f-wx) + v01*wx)*(1.0f-wy)
                           + (v10*(1.0f-wx) + v11*wx)*wy;
                float s = al * dist;

                float px = acc[vl*3+0] + s * ts[v*3+0];
                float py = acc[vl*3+1] + s * ts[v*3+1];
                float pz = acc[vl*3+2] + s * ts[v*3+2];

                float ox = 0.0f, oy = 0.0f, oz = 0.0f;
#pragma unroll
                for (int n = 0; n < NB; n++) {
                    float wn = W[n*NV + v];          // broadcast across lanes
                    float4 r0 = Gb[n*3 + 0];
                    float4 r1 = Gb[n*3 + 1];
                    float4 r2 = Gb[n*3 + 2];
                    ox = fmaf(wn, fmaf(r0.x, px, fmaf(r0.y, py, fmaf(r0.z, pz, r0.w))), ox);
                    oy = fmaf(wn, fmaf(r1.x, px, fmaf(r1.y, py, fmaf(r1.z, pz, r1.w))), oy);
                    oz = fmaf(wn, fmaf(r2.x, px, fmaf(r2.y, py, fmaf(r2.z, pz, r2.w))), oz);
                }
                int col = w*24 + vl*3;
                sm[lane*STG_PITCH + col + 0] = ox;
                sm[lane*STG_PITCH + col + 1] = oy;
                sm[lane*STG_PITCH + col + 2] = oz;
            }
        }
    }
    __syncthreads();

    // coalesced copy-out: row = batch, 192 consecutive comps
    for (int i = tid; i < BMB * BVC; i += 256) {
        int row = i / BVC;
        int col = i - row * BVC;
        int gc  = v0*3 + col;
        if (gc < NV3)
            out[(size_t)(b0 + row) * NV3 + gc] = sm[row*STG_PITCH + col];
    }
}

extern "C" void kernel_launch(void* const* d_in, const int* in_sizes, int n_in,
                              void* d_out, int out_size) {
    const float* theta  = (const float*)d_in[0];
    const float* tau    = (const float*)d_in[1];
    const float* alpha  = (const float*)d_in[2];
    const float* bsw    = (const float*)d_in[3];
    const float* W      = (const float*)d_in[4];
    const float* T      = (const float*)d_in[5];
    const float* P      = (const float*)d_in[6];
    const float* L      = (const float*)d_in[7];
    const float* ts     = (const float*)d_in[8];
    const float* L2P    = (const float*)d_in[9];
    const float* E      = (const float*)d_in[10];
    const float* uvgrid = (const float*)d_in[11];
    float* out = (float*)d_out;

    prep_kernel<<<1, 256>>>(theta, bsw, L2P);

    dim3 grid((NV + BVV - 1) / BVV, BATCH / BMB);
    hack_main_kernel<<<grid, 256>>>(P, E, T, W, ts, uvgrid, L, tau, alpha, out);
}

// round 4
// speedup vs baseline: 3.2521x; 3.2521x over previous
#include <cuda_runtime.h>
#include <cuda_bf16.h>
#include <math.h>
#include <stdint.h>

#define NB 8
#define BATCH 256
#define NV 14062
#define NV3 (NV*3)          // 42186
#define KD 120              // 63 pose-corr + 55 bsw + 2 zero pad (T excluded!)
#define KCH 40              // k per smem chunk (3 chunks)
#define NTILE 128           // comps per block
#define MTILE 64            // batches per block
#define NBLKS ((NV3 + NTILE - 1) / NTILE)   // 330

// scratch (allocation-free requirement -> device globals)
__device__ __align__(16) uint32_t g_coefA[BATCH * KD];   // tf32 bits, fragment order
__device__ __align__(16) float    g_bone[BATCH * NB * 12];
__device__ __align__(16) float    g_tt[(size_t)BATCH * NV3];  // GEMM result (43MB)

struct Aff { float r[9]; float t[3]; };

__device__ __forceinline__ Aff amul(const Aff& A, const Aff& B) {
    Aff C;
#pragma unroll
    for (int i = 0; i < 3; i++) {
#pragma unroll
        for (int j = 0; j < 3; j++)
            C.r[i*3+j] = A.r[i*3+0]*B.r[0*3+j] + A.r[i*3+1]*B.r[1*3+j] + A.r[i*3+2]*B.r[2*3+j];
        C.t[i] = A.r[i*3+0]*B.t[0] + A.r[i*3+1]*B.t[1] + A.r[i*3+2]*B.t[2] + A.t[i];
    }
    return C;
}

__device__ __forceinline__ Aff ainv_rigid(const Aff& A) {
    Aff C;
#pragma unroll
    for (int i = 0; i < 3; i++)
#pragma unroll
        for (int j = 0; j < 3; j++)
            C.r[i*3+j] = A.r[j*3+i];
#pragma unroll
    for (int i = 0; i < 3; i++)
        C.t[i] = -(C.r[i*3+0]*A.t[0] + C.r[i*3+1]*A.t[1] + C.r[i*3+2]*A.t[2]);
    return C;
}

__device__ __forceinline__ void rodrigues(const float* rv, float* R) {
    float x = rv[0], y = rv[1], z = rv[2];
    float d = x*x + y*y + z*z + 1e-12f;
    float ang = sqrtf(d);
    float inv = 1.0f / ang;
    float kx = x*inv, ky = y*inv, kz = z*inv;
    float s = sinf(ang), c = cosf(ang);
    float kk = kx*kx + ky*ky + kz*kz;
    float oc = 1.0f - c;
    R[0] = 1.0f + oc*(kx*kx - kk);
    R[1] = -s*kz + oc*(kx*ky);
    R[2] =  s*ky + oc*(kx*kz);
    R[3] =  s*kz + oc*(ky*kx);
    R[4] = 1.0f + oc*(ky*ky - kk);
    R[5] = -s*kx + oc*(ky*kz);
    R[6] = -s*ky + oc*(kz*kx);
    R[7] =  s*kx + oc*(kz*ky);
    R[8] = 1.0f + oc*(kz*kz - kk);
}

__device__ __forceinline__ uint32_t to_tf32(float f) {
    uint32_t u;
    asm("cvt.rna.tf32.f32 %0, %1;" : "=r"(u) : "f"(f));
    return u;
}

// One thread per batch: Rodrigues + FK chain + inverse binds; coef vector
// written in tf32 bits, in m16n8k8 A-fragment order:
//   idx = ((b64*15 + k8)*4 + mblk)*128 + lane*4 + reg
//   lane = g*4 + tig;  g=(b%16)&7, tig=(k%8)&3;  reg = ((k%8)>=4)*2 + ((b%16)>=8)
__global__ void prep_kernel(const float* __restrict__ theta,
                            const float* __restrict__ bsw,
                            const float* __restrict__ L2P) {
    int b = threadIdx.x;
    if (b >= BATCH) return;

    float R[NB][9];
#pragma unroll
    for (int n = 0; n < NB; n++)
        rodrigues(theta + (b*NB + n)*3, R[n]);

    float vals[KD];
#pragma unroll
    for (int n = 1; n < NB; n++)
#pragma unroll
        for (int i = 0; i < 3; i++)
#pragma unroll
            for (int j = 0; j < 3; j++)
                vals[(n-1)*9 + i*3 + j] = R[n][i*3+j] - (i == j ? 1.0f : 0.0f);
    for (int j = 0; j < 55; j++) vals[63 + j] = bsw[b*55 + j];
    vals[118] = 0.0f;
    vals[119] = 0.0f;

    int b64  = b >> 6;
    int mblk = (b >> 4) & 3;
    int r    = b & 15;
    int g    = r & 7;
    int hi   = r >> 3;
    for (int k = 0; k < KD; k++) {
        int k8 = k >> 3, t = k & 7, tig = t & 3, j2 = t >> 2;
        int lane = g*4 + tig;
        int reg  = j2*2 + hi;
        g_coefA[(((b64*15 + k8)*4 + mblk)*32 + lane)*4 + reg] = to_tf32(vals[k]);
    }

    Aff M, rest;
#pragma unroll
    for (int n = 0; n < NB; n++) {
        Aff l2p;
#pragma unroll
        for (int i = 0; i < 3; i++) {
#pragma unroll
            for (int j = 0; j < 3; j++) l2p.r[i*3+j] = L2P[n*16 + i*4 + j];
            l2p.t[i] = L2P[n*16 + i*4 + 3];
        }
        Aff loc;
#pragma unroll
        for (int i = 0; i < 9; i++) loc.r[i] = R[n][i];
        loc.t[0] = loc.t[1] = loc.t[2] = 0.0f;

        Aff An = amul(l2p, loc);
        M    = (n == 0) ? An  : amul(M, An);
        rest = (n == 0) ? l2p : amul(rest, l2p);

        Aff w2l = ainv_rigid(rest);
        Aff G = amul(M, w2l);

        float* gp = g_bone + b*(NB*12) + n*12;
#pragma unroll
        for (int i = 0; i < 3; i++) {
            gp[i*4+0] = G.r[i*3+0];
            gp[i*4+1] = G.r[i*3+1];
            gp[i*4+2] = G.r[i*3+2];
            gp[i*4+3] = G.t[i];
        }
    }
}

// tf32 tensor-core GEMM: g_tt[b][c] = sum_k coef[b][k] * Basis[k][c]
// Basis rows: k<63 -> P[(k+9)*NV3+c]; 63<=k<118 -> E[(k-63)*NV3+c]; else 0.
// Block: 256 thr (8 warps, 2M x 4N). Block tile M64 x N128. Warp tile 32x32.
__global__ __launch_bounds__(256, 3)
void gemm_kernel(const float* __restrict__ P,
                 const float* __restrict__ E) {
    __shared__ __align__(16) uint32_t sA[15*4*128];   // 30720 B, full-K A frags
    __shared__ __align__(16) uint32_t sB[5*16*66];    // 21120 B, one 40-k chunk

    const int tid   = threadIdx.x;
    const int lane  = tid & 31;
    const int wid   = tid >> 5;
    const int warpM = wid >> 2;      // 0..1
    const int warpN = wid & 3;       // 0..3
    const int cbase = blockIdx.x * NTILE;
    const int Mbase = blockIdx.y * MTILE;

    // load full A slice (fragment order, straight copy)
    {
        const float4* src = (const float4*)(g_coefA + Mbase*KD);
        float4* dst = (float4*)sA;
        for (int i = tid; i < (MTILE*KD)/4; i += 256) dst[i] = src[i];
    }

    float acc[2][4][4];
#pragma unroll
    for (int mi = 0; mi < 2; mi++)
#pragma unroll
        for (int ni = 0; ni < 4; ni++)
#pragma unroll
            for (int q = 0; q < 4; q++) acc[mi][ni][q] = 0.0f;

    for (int kc = 0; kc < 3; kc++) {
        __syncthreads();
        // fill B chunk [KCH=40 x 128] in fragment order
        for (int idx = tid; idx < KCH*NTILE; idx += 256) {
            int kl = idx >> 7;
            int cl = idx & 127;
            int k  = kc*KCH + kl;
            int c  = cbase + cl;
            float v = 0.0f;
            if (c < NV3) {
                if (k < 63)       v = P[(size_t)(k+9)*NV3 + c];
                else if (k < 118) v = E[(size_t)(k-63)*NV3 + c];
            }
            int k8l = kl >> 3, t = kl & 7, tig = t & 3, j = t >> 2;
            int nblk = cl >> 3, gg = cl & 7;
            sB[k8l*1056 + nblk*66 + (gg*4 + tig)*2 + j] = to_tf32(v);
        }
        __syncthreads();

#pragma unroll
        for (int k8l = 0; k8l < 5; k8l++) {
            const int k8g = kc*5 + k8l;
            uint32_t a[2][4];
#pragma unroll
            for (int mi = 0; mi < 2; mi++) {
                uint4 av = *(const uint4*)&sA[((k8g*4 + warpM*2 + mi)*32 + lane)*4];
                a[mi][0] = av.x; a[mi][1] = av.y; a[mi][2] = av.z; a[mi][3] = av.w;
            }
            uint32_t bf[4][2];
#pragma unroll
            for (int ni = 0; ni < 4; ni++) {
                uint2 bv = *(const uint2*)&sB[k8l*1056 + (warpN*4 + ni)*66 + lane*2];
                bf[ni][0] = bv.x; bf[ni][1] = bv.y;
            }
#pragma unroll
            for (int mi = 0; mi < 2; mi++)
#pragma unroll
                for (int ni = 0; ni < 4; ni++) {
                    asm volatile(
                        "mma.sync.aligned.m16n8k8.row.col.f32.tf32.tf32.f32 "
                        "{%0,%1,%2,%3}, {%4,%5,%6,%7}, {%8,%9}, {%0,%1,%2,%3};"
                        : "+f"(acc[mi][ni][0]), "+f"(acc[mi][ni][1]),
                          "+f"(acc[mi][ni][2]), "+f"(acc[mi][ni][3])
                        : "r"(a[mi][0]), "r"(a[mi][1]), "r"(a[mi][2]), "r"(a[mi][3]),
                          "r"(bf[ni][0]), "r"(bf[ni][1]));
                }
        }
    }

    // store C fragments (32B-contiguous segments per 4-lane group)
    const int gg  = lane >> 2;
    const int tt4 = lane & 3;
#pragma unroll
    for (int mi = 0; mi < 2; mi++) {
#pragma unroll
        for (int ni = 0; ni < 4; ni++) {
            int row = Mbase + warpM*32 + mi*16 + gg;
            int col = cbase + warpN*32 + ni*8 + tt4*2;
            if (col < NV3) {
                *(float2*)&g_tt[(size_t)row*NV3 + col] =
                    make_float2(acc[mi][ni][0], acc[mi][ni][1]);
                *(float2*)&g_tt[(size_t)(row+8)*NV3 + col] =
                    make_float2(acc[mi][ni][2], acc[mi][ni][3]);
            }
        }
    }
}

// Epilogue: T (exact) + larynx displacement + skinning. One thread per (b, v).
__global__ __launch_bounds__(256)
void epi_kernel(const float* __restrict__ T,
                const float* __restrict__ W,
                const float* __restrict__ ts,
                const float* __restrict__ uvgrid,
                const float* __restrict__ L,
                const float* __restrict__ tau,
                const float* __restrict__ alpha,
                float* __restrict__ out) {
    const int v = blockIdx.x * 256 + threadIdx.x;
    const int b = blockIdx.y;
    if (v >= NV) return;

    const float tb = tau[b];
    const float al = alpha[b];

    // bilinear sample of L (256x256), align_corners=True, border clamp
    float ux = uvgrid[v*2+0], uy = uvgrid[v*2+1];
    float x = fminf(fmaxf(ux * 255.0f, 0.0f), 255.0f);
    float y = fminf(fmaxf((uy + tb) * 255.0f, 0.0f), 255.0f);
    int x0 = (int)floorf(x), y0 = (int)floorf(y);
    int x1 = min(x0 + 1, 255), y1 = min(y0 + 1, 255);
    float wx = x - (float)x0, wy = y - (float)y0;
    float v00 = L[y0*256 + x0], v01 = L[y0*256 + x1];
    float v10 = L[y1*256 + x0], v11 = L[y1*256 + x1];
    float dist = (v00*(1.0f-wx) + v01*wx)*(1.0f-wy)
               + (v10*(1.0f-wx) + v11*wx)*wy;
    float s = al * dist;

    const float* c = g_tt + (size_t)b*NV3 + (size_t)v*3;
    float px = c[0] + T[v*3+0] + s * ts[v*3+0];
    float py = c[1] + T[v*3+1] + s * ts[v*3+1];
    float pz = c[2] + T[v*3+2] + s * ts[v*3+2];

    const float4* Gb = (const float4*)(g_bone + b*(NB*12));
    float ox = 0.0f, oy = 0.0f, oz = 0.0f;
#pragma unroll
    for (int n = 0; n < NB; n++) {
        float wn = W[n*NV + v];
        float4 r0 = Gb[n*3 + 0];
        float4 r1 = Gb[n*3 + 1];
        float4 r2 = Gb[n*3 + 2];
        ox = fmaf(wn, fmaf(r0.x, px, fmaf(r0.y, py, fmaf(r0.z, pz, r0.w))), ox);
        oy = fmaf(wn, fmaf(r1.x, px, fmaf(r1.y, py, fmaf(r1.z, pz, r1.w))), oy);
        oz = fmaf(wn, fmaf(r2.x, px, fmaf(r2.y, py, fmaf(r2.z, pz, r2.w))), oz);
    }
    size_t base = (size_t)b * NV3 + (size_t)v * 3;
    out[base + 0] = ox;
    out[base + 1] = oy;
    out[base + 2] = oz;
}

extern "C" void kernel_launch(void* const* d_in, const int* in_sizes, int n_in,
                              void* d_out, int out_size) {
    const float* theta  = (const float*)d_in[0];
    const float* tau    = (const float*)d_in[1];
    const float* alpha  = (const float*)d_in[2];
    const float* bsw    = (const float*)d_in[3];
    const float* W      = (const float*)d_in[4];
    const float* T      = (const float*)d_in[5];
    const float* P      = (const float*)d_in[6];
    const float* L      = (const float*)d_in[7];
    const float* ts     = (const float*)d_in[8];
    const float* L2P    = (const float*)d_in[9];
    const float* E      = (const float*)d_in[10];
    const float* uvgrid = (const float*)d_in[11];
    float* out = (float*)d_out;

    prep_kernel<<<1, 256>>>(theta, bsw, L2P);

    dim3 ggrid(NBLKS, BATCH / MTILE);
    gemm_kernel<<<ggrid, 256>>>(P, E);

    dim3 egrid((NV + 255) / 256, BATCH);
    epi_kernel<<<egrid, 256>>>(T, W, ts, uvgrid, L, tau, alpha, out);
}

// round 5
// speedup vs baseline: 4.0026x; 1.2308x over previous
#include <cuda_runtime.h>
#include <cuda_bf16.h>
#include <math.h>
#include <stdint.h>

#define NB 8
#define BATCH 256
#define NV 14062
#define NV3 (NV*3)          // 42186
#define KD 120              // 63 pose-corr + 55 bsw + 2 zero pad (T excluded)
#define KCH 40              // k per smem chunk (3 chunks)
#define NTILE 96            // comps per block = 32 vertices exactly
#define VTILE 32
#define MTILE 64            // batches per block
#define NBLKS ((NV3 + NTILE - 1) / NTILE)   // 440
#define ST_PITCH 100        // staging row pitch (floats)

// scratch (allocation-free requirement -> device globals)
__device__ __align__(16) uint32_t g_coefA[BATCH * KD];   // tf32 bits, A-fragment order
__device__ __align__(16) float    g_R[BATCH * NB * 9];   // per-bone rotations
__device__ __align__(16) float    g_bone[BATCH * NB * 12];

struct Aff { float r[9]; float t[3]; };

__device__ __forceinline__ Aff amul(const Aff& A, const Aff& B) {
    Aff C;
#pragma unroll
    for (int i = 0; i < 3; i++) {
#pragma unroll
        for (int j = 0; j < 3; j++)
            C.r[i*3+j] = A.r[i*3+0]*B.r[0*3+j] + A.r[i*3+1]*B.r[1*3+j] + A.r[i*3+2]*B.r[2*3+j];
        C.t[i] = A.r[i*3+0]*B.t[0] + A.r[i*3+1]*B.t[1] + A.r[i*3+2]*B.t[2] + A.t[i];
    }
    return C;
}

__device__ __forceinline__ Aff ainv_rigid(const Aff& A) {
    Aff C;
#pragma unroll
    for (int i = 0; i < 3; i++)
#pragma unroll
        for (int j = 0; j < 3; j++)
            C.r[i*3+j] = A.r[j*3+i];
#pragma unroll
    for (int i = 0; i < 3; i++)
        C.t[i] = -(C.r[i*3+0]*A.t[0] + C.r[i*3+1]*A.t[1] + C.r[i*3+2]*A.t[2]);
    return C;
}

__device__ __forceinline__ void rodrigues(const float* rv, float* R) {
    float x = rv[0], y = rv[1], z = rv[2];
    float d = x*x + y*y + z*z + 1e-12f;
    float ang = sqrtf(d);
    float inv = 1.0f / ang;
    float kx = x*inv, ky = y*inv, kz = z*inv;
    float s = sinf(ang), c = cosf(ang);
    float kk = kx*kx + ky*ky + kz*kz;
    float oc = 1.0f - c;
    R[0] = 1.0f + oc*(kx*kx - kk);
    R[1] = -s*kz + oc*(kx*ky);
    R[2] =  s*ky + oc*(kx*kz);
    R[3] =  s*kz + oc*(ky*kx);
    R[4] = 1.0f + oc*(ky*ky - kk);
    R[5] = -s*kx + oc*(ky*kz);
    R[6] = -s*ky + oc*(kz*kx);
    R[7] =  s*kx + oc*(kz*ky);
    R[8] = 1.0f + oc*(kz*kz - kk);
}

__device__ __forceinline__ uint32_t to_tf32(float f) {
    uint32_t u;
    asm("cvt.rna.tf32.f32 %0, %1;" : "=r"(u) : "f"(f));
    return u;
}

// write coef value k for batch b into m16n8k8 A-fragment-ordered g_coefA
__device__ __forceinline__ void store_coef(int b, int k, float v) {
    int b64  = b >> 6;
    int mblk = (b >> 4) & 3;
    int r    = b & 15;
    int g    = r & 7;
    int hi   = r >> 3;
    int k8 = k >> 3, t = k & 7, tig = t & 3, j2 = t >> 2;
    int lane = g*4 + tig;
    int reg  = j2*2 + hi;
    g_coefA[(((b64*15 + k8)*4 + mblk)*32 + lane)*4 + reg] = to_tf32(v);
}

// prep1: one block per batch; threads 0-7 do one Rodrigues each (+ theta_zero
// coefs for bones 1-7), threads 8-62 copy bsw coefs. k=118,119 stay zero
// (device globals are zero-initialized and never written).
__global__ void prep1_kernel(const float* __restrict__ theta,
                             const float* __restrict__ bsw) {
    const int b = blockIdx.x;
    const int t = threadIdx.x;
    if (t < 8) {
        float R[9];
        rodrigues(theta + (b*NB + t)*3, R);
#pragma unroll
        for (int i = 0; i < 9; i++) g_R[(b*NB + t)*9 + i] = R[i];
        if (t >= 1) {
#pragma unroll
            for (int i = 0; i < 3; i++)
#pragma unroll
                for (int j = 0; j < 3; j++)
                    store_coef(b, (t-1)*9 + i*3 + j, R[i*3+j] - (i == j ? 1.0f : 0.0f));
        }
    } else if (t < 63) {
        int j = t - 8;
        store_coef(b, 63 + j, bsw[b*55 + j]);
    }
}

// prep2: FK chain + inverse binds per batch (spread over 8 SMs).
__global__ void prep2_kernel(const float* __restrict__ L2P) {
    const int b = blockIdx.x * 32 + threadIdx.x;
    if (b >= BATCH) return;

    Aff M, rest;
#pragma unroll
    for (int n = 0; n < NB; n++) {
        Aff l2p;
#pragma unroll
        for (int i = 0; i < 3; i++) {
#pragma unroll
            for (int j = 0; j < 3; j++) l2p.r[i*3+j] = L2P[n*16 + i*4 + j];
            l2p.t[i] = L2P[n*16 + i*4 + 3];
        }
        Aff loc;
#pragma unroll
        for (int i = 0; i < 9; i++) loc.r[i] = g_R[(b*NB + n)*9 + i];
        loc.t[0] = loc.t[1] = loc.t[2] = 0.0f;

        Aff An = amul(l2p, loc);
        M    = (n == 0) ? An  : amul(M, An);
        rest = (n == 0) ? l2p : amul(rest, l2p);

        Aff w2l = ainv_rigid(rest);
        Aff G = amul(M, w2l);

        float* gp = g_bone + b*(NB*12) + n*12;
#pragma unroll
        for (int i = 0; i < 3; i++) {
            gp[i*4+0] = G.r[i*3+0];
            gp[i*4+1] = G.r[i*3+1];
            gp[i*4+2] = G.r[i*3+2];
            gp[i*4+3] = G.t[i];
        }
    }
}

// Fused tf32 GEMM + epilogue. Block tile: 64 batches x 96 comps (32 verts).
// 8 warps = 2M x 4N; warp tile 32x24 (2 m16 x 3 n8 frags).
// After MMA: stage C in smem, then larynx + T + LBS epilogue, direct out write.
#define SA_WORDS (15*4*128)          // 7680
#define SB_WORDS (5*12*66)           // 3960 per chunk
#define SMEM_BYTES ((SA_WORDS + SB_WORDS) * 4)   // 46560 >= 64*100*4 = 25600

__global__ __launch_bounds__(256, 3)
void fused_kernel(const float* __restrict__ P,
                  const float* __restrict__ E,
                  const float* __restrict__ T,
                  const float* __restrict__ W,
                  const float* __restrict__ ts,
                  const float* __restrict__ uvgrid,
                  const float* __restrict__ L,
                  const float* __restrict__ tau,
                  const float* __restrict__ alpha,
                  float* __restrict__ out) {
    __shared__ __align__(16) char smem_raw[SMEM_BYTES];
    uint32_t* sA = (uint32_t*)smem_raw;
    uint32_t* sB = sA + SA_WORDS;
    float*    st = (float*)smem_raw;    // staging alias (after MMA)

    const int tid   = threadIdx.x;
    const int lane  = tid & 31;
    const int wid   = tid >> 5;
    const int warpM = wid >> 2;      // 0..1
    const int warpN = wid & 3;       // 0..3
    const int cbase = blockIdx.x * NTILE;
    const int vbase = blockIdx.x * VTILE;
    const int Mbase = blockIdx.y * MTILE;

    // load full-K A slice (already fragment-ordered)
    {
        const float4* src = (const float4*)(g_coefA + Mbase*KD);
        float4* dst = (float4*)sA;
        for (int i = tid; i < (MTILE*KD)/4; i += 256) dst[i] = src[i];
    }

    float acc[2][3][4];
#pragma unroll
    for (int mi = 0; mi < 2; mi++)
#pragma unroll
        for (int ni = 0; ni < 3; ni++)
#pragma unroll
            for (int q = 0; q < 4; q++) acc[mi][ni][q] = 0.0f;

    for (int kc = 0; kc < 3; kc++) {
        __syncthreads();
        // fill B chunk [KCH x 96] in fragment order
        for (int idx = tid; idx < KCH*NTILE; idx += 256) {
            int kl = idx / NTILE;
            int cl = idx - kl*NTILE;
            int k  = kc*KCH + kl;
            int c  = cbase + cl;
            float v = 0.0f;
            if (c < NV3) {
                if (k < 63)       v = P[(size_t)(k+9)*NV3 + c];
                else if (k < 118) v = E[(size_t)(k-63)*NV3 + c];
            }
            int k8l = kl >> 3, t = kl & 7, tig = t & 3, j = t >> 2;
            int nblk = cl >> 3, gg = cl & 7;
            sB[k8l*(12*66) + nblk*66 + (gg*4 + tig)*2 + j] = to_tf32(v);
        }
        __syncthreads();

#pragma unroll
        for (int k8l = 0; k8l < 5; k8l++) {
            const int k8g = kc*5 + k8l;
            uint32_t a[2][4];
#pragma unroll
            for (int mi = 0; mi < 2; mi++) {
                uint4 av = *(const uint4*)&sA[((k8g*4 + warpM*2 + mi)*32 + lane)*4];
                a[mi][0] = av.x; a[mi][1] = av.y; a[mi][2] = av.z; a[mi][3] = av.w;
            }
            uint32_t bf[3][2];
#pragma unroll
            for (int ni = 0; ni < 3; ni++) {
                uint2 bv = *(const uint2*)&sB[k8l*(12*66) + (warpN*3 + ni)*66 + lane*2];
                bf[ni][0] = bv.x; bf[ni][1] = bv.y;
            }
#pragma unroll
            for (int mi = 0; mi < 2; mi++)
#pragma unroll
                for (int ni = 0; ni < 3; ni++) {
                    asm volatile(
                        "mma.sync.aligned.m16n8k8.row.col.f32.tf32.tf32.f32 "
                        "{%0,%1,%2,%3}, {%4,%5,%6,%7}, {%8,%9}, {%0,%1,%2,%3};"
                        : "+f"(acc[mi][ni][0]), "+f"(acc[mi][ni][1]),
                          "+f"(acc[mi][ni][2]), "+f"(acc[mi][ni][3])
                        : "r"(a[mi][0]), "r"(a[mi][1]), "r"(a[mi][2]), "r"(a[mi][3]),
                          "r"(bf[ni][0]), "r"(bf[ni][1]));
                }
        }
    }

    // stage C tile into smem [64 rows x 96 cols], pitch ST_PITCH
    __syncthreads();   // sA/sB dead
    {
        const int gg  = lane >> 2;
        const int tt4 = lane & 3;
#pragma unroll
        for (int mi = 0; mi < 2; mi++) {
#pragma unroll
            for (int ni = 0; ni < 3; ni++) {
                int row = warpM*32 + mi*16 + gg;
                int col = warpN*24 + ni*8 + tt4*2;
                *(float2*)&st[row*ST_PITCH + col] =
                    make_float2(acc[mi][ni][0], acc[mi][ni][1]);
                *(float2*)&st[(row+8)*ST_PITCH + col] =
                    make_float2(acc[mi][ni][2], acc[mi][ni][3]);
            }
        }
    }
    __syncthreads();

    // Epilogue: each thread owns one vertex column (lane-contiguous) and 8
    // batch rows (warp-uniform -> broadcast bone/tau/alpha loads).
    {
        const int vl = tid & 31;
        const int r0 = tid >> 5;
        const int v  = vbase + vl;
        if (v < NV) {
            const float Tx = T[v*3+0], Ty = T[v*3+1], Tz = T[v*3+2];
            const float tsx = ts[v*3+0], tsy = ts[v*3+1], tsz = ts[v*3+2];
            float w8[NB];
#pragma unroll
            for (int n = 0; n < NB; n++) w8[n] = W[n*NV + v];
            const float ux = uvgrid[v*2+0], uy = uvgrid[v*2+1];
            // x-half of bilinear sample is tau-independent: hoist
            float x = fminf(fmaxf(ux * 255.0f, 0.0f), 255.0f);
            int x0 = (int)floorf(x);
            int x1 = min(x0 + 1, 255);
            float wx = x - (float)x0;

#pragma unroll
            for (int i = 0; i < 8; i++) {
                const int row = r0 + i*8;
                const int b = Mbase + row;
                const float tb = tau[b];
                const float al = alpha[b];

                float y = fminf(fmaxf((uy + tb) * 255.0f, 0.0f), 255.0f);
                int y0 = (int)floorf(y);
                int y1 = min(y0 + 1, 255);
                float wy = y - (float)y0;
                float v00 = L[y0*256 + x0], v01 = L[y0*256 + x1];
                float v10 = L[y1*256 + x0], v11 = L[y1*256 + x1];
                float dist = (v00*(1.0f-wx) + v01*wx)*(1.0f-wy)
                           + (v10*(1.0f-wx) + v11*wx)*wy;
                float s = al * dist;

                float px = st[row*ST_PITCH + vl*3+0] + Tx + s*tsx;
                float py = st[row*ST_PITCH + vl*3+1] + Ty + s*tsy;
                float pz = st[row*ST_PITCH + vl*3+2] + Tz + s*tsz;

                const float4* Gb = (const float4*)(g_bone + b*(NB*12));
                float ox = 0.0f, oy = 0.0f, oz = 0.0f;
#pragma unroll
                for (int n = 0; n < NB; n++) {
                    float4 q0 = Gb[n*3 + 0];   // broadcast across warp
                    float4 q1 = Gb[n*3 + 1];
                    float4 q2 = Gb[n*3 + 2];
                    float wn = w8[n];
                    ox = fmaf(wn, fmaf(q0.x, px, fmaf(q0.y, py, fmaf(q0.z, pz, q0.w))), ox);
                    oy = fmaf(wn, fmaf(q1.x, px, fmaf(q1.y, py, fmaf(q1.z, pz, q1.w))), oy);
                    oz = fmaf(wn, fmaf(q2.x, px, fmaf(q2.y, py, fmaf(q2.z, pz, q2.w))), oz);
                }
                size_t base = (size_t)b * NV3 + (size_t)v * 3;
                out[base + 0] = ox;
                out[base + 1] = oy;
                out[base + 2] = oz;
            }
        }
    }
}

extern "C" void kernel_launch(void* const* d_in, const int* in_sizes, int n_in,
                              void* d_out, int out_size) {
    const float* theta  = (const float*)d_in[0];
    const float* tau    = (const float*)d_in[1];
    const float* alpha  = (const float*)d_in[2];
    const float* bsw    = (const float*)d_in[3];
    const float* W      = (const float*)d_in[4];
    const float* T      = (const float*)d_in[5];
    const float* P      = (const float*)d_in[6];
    const float* L      = (const float*)d_in[7];
    const float* ts     = (const float*)d_in[8];
    const float* L2P    = (const float*)d_in[9];
    const float* E      = (const float*)d_in[10];
    const float* uvgrid = (const float*)d_in[11];
    float* out = (float*)d_out;

    prep1_kernel<<<BATCH, 64>>>(theta, bsw);
    prep2_kernel<<<8, 32>>>(L2P);

    dim3 ggrid(NBLKS, BATCH / MTILE);
    fused_kernel<<<ggrid, 256>>>(P, E, T, W, ts, uvgrid, L, tau, alpha, out);
}